// round 7
// baseline (speedup 1.0000x reference)
#include <cuda_runtime.h>
#include <cstdint>

#define ND 4096
#define NE 64
#define NTOK 16384
#define TOK_CTA 64
#define NTHREADS 128
#define KSPLIT 2
#define KHALF (ND / KSPLIT)     // 2048
#define KC 64
#define NSTAGE (KHALF / KC)     // 32
#define PLANE 8192              // [4 g][64 n][4 j] * 8B
#define BUFB (3 * PLANE)        // hi, mid, lo planes

// partial logits, one slab per K-split half (8 MB static scratch)
__device__ float g_part[KSPLIT][NTOK][NE];

// round-to-nearest 3-way split: h = hi + mid + lo + eps, |eps| <= 2^-27|h|, unbiased.
__device__ __forceinline__ void cvt_split_pair(float h0, float h1,
                                               uint32_t& hi2, uint32_t& mid2, uint32_t& lo2) {
    asm("cvt.rn.bf16x2.f32 %0, %1, %2;" : "=r"(hi2) : "f"(h1), "f"(h0));   // lo half = h0
    float f0 = __uint_as_float(hi2 << 16);
    float f1 = __uint_as_float(hi2 & 0xFFFF0000u);
    float r0 = h0 - f0;
    float r1 = h1 - f1;
    asm("cvt.rn.bf16x2.f32 %0, %1, %2;" : "=r"(mid2) : "f"(r1), "f"(r0));
    float g0 = __uint_as_float(mid2 << 16);
    float g1 = __uint_as_float(mid2 & 0xFFFF0000u);
    float q0 = r0 - g0;
    float q1 = r1 - g1;
    asm("cvt.rn.bf16x2.f32 %0, %1, %2;" : "=r"(lo2) : "f"(q1), "f"(q0));
}

#define MMA(c, a, b0_, b1_) \
    asm volatile("mma.sync.aligned.m16n8k16.row.col.f32.bf16.bf16.f32 " \
        "{%0,%1,%2,%3}, {%4,%5,%6,%7}, {%8,%9}, {%0,%1,%2,%3};" \
        : "+f"((c)[0]), "+f"((c)[1]), "+f"((c)[2]), "+f"((c)[3]) \
        : "r"((a)[0]), "r"((a)[1]), "r"((a)[2]), "r"((a)[3]), "r"(b0_), "r"(b1_))

__global__ __launch_bounds__(NTHREADS, 3)
void router_gemm_kernel(const float* __restrict__ hs,
                        const float* __restrict__ W)
{
    __shared__ __align__(16) char smem[2 * BUFB];   // 49152 B

    const int tid  = threadIdx.x;
    const int lane = tid & 31;
    const int warp = tid >> 5;
    const int j    = lane & 3;     // thread-in-group (k-pair selector)
    const int qr   = lane >> 2;    // group id (row / n selector)
    const int tok0 = blockIdx.x * TOK_CTA;
    const int kz   = blockIdx.y;   // K-split index
    const int kbase = kz * KHALF;

    const int wn0 = 8 * warp + qr;

    const float* aRow = hs + (size_t)(tok0 + warp * 16 + qr) * ND + kbase + 2 * j;

    float acc[8][4];
#pragma unroll
    for (int t = 0; t < 8; t++)
#pragma unroll
        for (int c = 0; c < 4; c++) acc[t][c] = 0.f;

    float2 wpre[16];

    // ---- prologue: load + convert W stage 0 into buf0 ----
#pragma unroll
    for (int h = 0; h < 2; h++) {
        const float* wr = W + (size_t)(wn0 + 32 * h) * ND + kbase + 2 * j;
#pragma unroll
        for (int g = 0; g < 4; g++) {
            wpre[h * 8 + g * 2 + 0] = *(const float2*)(wr + 16 * g);
            wpre[h * 8 + g * 2 + 1] = *(const float2*)(wr + 16 * g + 8);
        }
    }
#pragma unroll
    for (int h = 0; h < 2; h++) {
        int n = wn0 + 32 * h;
#pragma unroll
        for (int g = 0; g < 4; g++) {
            uint32_t h0, m0, l0, h1, m1, l1;
            float2 p0 = wpre[h * 8 + g * 2], p1 = wpre[h * 8 + g * 2 + 1];
            cvt_split_pair(p0.x, p0.y, h0, m0, l0);
            cvt_split_pair(p1.x, p1.y, h1, m1, l1);
            char* d = smem + (g * 64 + n) * 32 + j * 8;
            *(uint2*)(d)             = make_uint2(h0, h1);
            *(uint2*)(d + PLANE)     = make_uint2(m0, m1);
            *(uint2*)(d + 2 * PLANE) = make_uint2(l0, l1);
        }
    }
    __syncthreads();

    // ---- main loop over K stages ----
    for (int s = 0; s < NSTAGE; s++) {
        if (s + 1 < NSTAGE) {
            const int kn = (s + 1) * KC;
#pragma unroll
            for (int h = 0; h < 2; h++) {
                const float* wr = W + (size_t)(wn0 + 32 * h) * ND + kbase + kn + 2 * j;
#pragma unroll
                for (int g = 0; g < 4; g++) {
                    wpre[h * 8 + g * 2 + 0] = *(const float2*)(wr + 16 * g);
                    wpre[h * 8 + g * 2 + 1] = *(const float2*)(wr + 16 * g + 8);
                }
            }
        }

        const char* buf = smem + (s & 1) * BUFB;
        const int k0 = s * KC;

        float2 a0 = *(const float2*)(aRow + k0);
        float2 a1 = *(const float2*)(aRow + 8 * ND + k0);
        float2 a2 = *(const float2*)(aRow + k0 + 8);
        float2 a3 = *(const float2*)(aRow + 8 * ND + k0 + 8);

#pragma unroll
        for (int g = 0; g < 4; g++) {
            float2 p0, p1, p2, p3;
            if (g < 3) {
                const int kg = k0 + 16 * (g + 1);
                p0 = *(const float2*)(aRow + kg);
                p1 = *(const float2*)(aRow + 8 * ND + kg);
                p2 = *(const float2*)(aRow + kg + 8);
                p3 = *(const float2*)(aRow + 8 * ND + kg + 8);
            }
            uint32_t aH[4], aM[4], aL[4];
            cvt_split_pair(a0.x, a0.y, aH[0], aM[0], aL[0]);
            cvt_split_pair(a1.x, a1.y, aH[1], aM[1], aL[1]);
            cvt_split_pair(a2.x, a2.y, aH[2], aM[2], aL[2]);
            cvt_split_pair(a3.x, a3.y, aH[3], aM[3], aL[3]);

            const char* bb = buf + (size_t)(g * 64 + qr) * 32 + j * 8;
#pragma unroll
            for (int t = 0; t < 8; t++) {
                const char* bt = bb + t * 256;            // +8 n rows
                uint2 bh = *(const uint2*)(bt);
                uint2 bm = *(const uint2*)(bt + PLANE);
                uint2 bl = *(const uint2*)(bt + 2 * PLANE);
                MMA(acc[t], aH, bh.x, bh.y);
                MMA(acc[t], aM, bh.x, bh.y);
                MMA(acc[t], aL, bh.x, bh.y);
                MMA(acc[t], aH, bm.x, bm.y);
                MMA(acc[t], aM, bm.x, bm.y);
                MMA(acc[t], aH, bl.x, bl.y);
            }
            if (g < 3) { a0 = p0; a1 = p1; a2 = p2; a3 = p3; }
        }

        if (s + 1 < NSTAGE) {
            char* nb = smem + ((s + 1) & 1) * BUFB;
#pragma unroll
            for (int h = 0; h < 2; h++) {
                int n = wn0 + 32 * h;
#pragma unroll
                for (int g = 0; g < 4; g++) {
                    uint32_t h0, m0, l0, h1, m1, l1;
                    float2 p0 = wpre[h * 8 + g * 2], p1 = wpre[h * 8 + g * 2 + 1];
                    cvt_split_pair(p0.x, p0.y, h0, m0, l0);
                    cvt_split_pair(p1.x, p1.y, h1, m1, l1);
                    char* d = nb + (g * 64 + n) * 32 + j * 8;
                    *(uint2*)(d)             = make_uint2(h0, h1);
                    *(uint2*)(d + PLANE)     = make_uint2(m0, m1);
                    *(uint2*)(d + 2 * PLANE) = make_uint2(l0, l1);
                }
            }
            __syncthreads();
        }
    }

    // ---- epilogue: write fp32 partial logits ----
    const int row0 = tok0 + warp * 16 + qr;
#pragma unroll
    for (int t = 0; t < 8; t++) {
        const int e = 8 * t + 2 * j;
        *(float2*)&g_part[kz][row0][e]     = make_float2(acc[t][0], acc[t][1]);
        *(float2*)&g_part[kz][row0 + 8][e] = make_float2(acc[t][2], acc[t][3]);
    }
}

// ---- kernel 2: add the two K-halves, top-2 + softmax ----
__global__ __launch_bounds__(128)
void router_reduce_kernel(float* __restrict__ out)
{
    __shared__ float LG[128][65];
    const int tid  = threadIdx.x;
    const int tok0 = blockIdx.x * 128;

    const float4* p0 = (const float4*)&g_part[0][tok0][0];
    const float4* p1 = (const float4*)&g_part[1][tok0][0];
#pragma unroll
    for (int i = tid; i < 128 * NE / 4; i += 128) {
        float4 a = p0[i];
        float4 b = p1[i];
        const int base = i * 4;
        const int r = base >> 6, c = base & 63;
        LG[r][c + 0] = a.x + b.x;
        LG[r][c + 1] = a.y + b.y;
        LG[r][c + 2] = a.z + b.z;
        LG[r][c + 3] = a.w + b.w;
    }
    __syncthreads();

    float m1 = -3.4e38f, m2 = -3.4e38f;
    int i1 = 0, i2 = 0;
#pragma unroll 8
    for (int e = 0; e < NE; e++) {
        float v = LG[tid][e];
        if (v > m1) { m2 = m1; i2 = i1; m1 = v; i1 = e; }
        else if (v > m2) { m2 = v; i2 = e; }
    }
    float ex = __expf(m2 - m1);
    float s1 = 1.0f / (1.0f + ex);
    const int tok = tok0 + tid;
    out[2 * tok]     = s1;
    out[2 * tok + 1] = ex * s1;
    out[2 * NTOK + 2 * tok]     = (float)i1;
    out[2 * NTOK + 2 * tok + 1] = (float)i2;
}

extern "C" void kernel_launch(void* const* d_in, const int* in_sizes, int n_in,
                              void* d_out, int out_size)
{
    const float* hs = (const float*)d_in[0];   // (4, 4096, 4096) fp32
    const float* W  = (const float*)d_in[1];   // (64, 4096) fp32
    float* out      = (float*)d_out;           // [scores 32768][indices 32768]
    (void)in_sizes; (void)n_in; (void)out_size;

    dim3 grid(NTOK / TOK_CTA, KSPLIT);         // (256, 2)
    router_gemm_kernel<<<grid, NTHREADS>>>(hs, W);
    router_reduce_kernel<<<NTOK / 128, 128>>>(out);
}

// round 9
// speedup vs baseline: 1.3070x; 1.3070x over previous
#include <cuda_runtime.h>
#include <cstdint>

#define ND 4096
#define NE 64
#define NTOK 16384
#define TOK_CTA 64
#define NTHREADS 128
#define KC 64
#define NSTAGE (ND / KC)        // 64
#define PLANE 8192              // [4 g][64 n][4 j] * 8B
#define BUFB (2 * PLANE)        // hi, mid planes

// round-to-nearest fp16 2-way split: h = hi + mid + q, |q| <= 2^-22|h|, unbiased.
__device__ __forceinline__ void cvt_split_pair(float h0, float h1,
                                               uint32_t& hi2, uint32_t& mid2) {
    asm("cvt.rn.f16x2.f32 %0, %1, %2;" : "=r"(hi2) : "f"(h1), "f"(h0));   // lo half = h0
    float f0, f1;
    asm("{.reg .f16 a, b;\n\t mov.b32 {a, b}, %2;\n\t"
        "cvt.f32.f16 %0, a;\n\t cvt.f32.f16 %1, b;}"
        : "=f"(f0), "=f"(f1) : "r"(hi2));
    float r0 = h0 - f0;
    float r1 = h1 - f1;
    asm("cvt.rn.f16x2.f32 %0, %1, %2;" : "=r"(mid2) : "f"(r1), "f"(r0));
}

#define MMA(c, a, b0_, b1_) \
    asm volatile("mma.sync.aligned.m16n8k16.row.col.f32.f16.f16.f32 " \
        "{%0,%1,%2,%3}, {%4,%5,%6,%7}, {%8,%9}, {%0,%1,%2,%3};" \
        : "+f"((c)[0]), "+f"((c)[1]), "+f"((c)[2]), "+f"((c)[3]) \
        : "r"((a)[0]), "r"((a)[1]), "r"((a)[2]), "r"((a)[3]), "r"(b0_), "r"(b1_))

__global__ __launch_bounds__(NTHREADS, 2)
void topk_router_kernel(const float* __restrict__ hs,
                        const float* __restrict__ W,
                        float* __restrict__ out)
{
    __shared__ __align__(16) char smem[2 * BUFB];   // 32768 B

    const int tid  = threadIdx.x;
    const int lane = tid & 31;
    const int warp = tid >> 5;
    const int j    = lane & 3;     // thread-in-group (k-pair selector)
    const int qr   = lane >> 2;    // group id (row / n selector)
    const int tok0 = blockIdx.x * TOK_CTA;

    const int wn0 = 8 * warp + qr;
    const float* aRow = hs + (size_t)(tok0 + warp * 16 + qr) * ND + 2 * j;

    float acc[8][4];
#pragma unroll
    for (int t = 0; t < 8; t++)
#pragma unroll
        for (int c = 0; c < 4; c++) acc[t][c] = 0.f;

    float2 wpre[16];

    // ---- prologue: load + convert W stage 0 into buf0 ----
#pragma unroll
    for (int h = 0; h < 2; h++) {
        const float* wr = W + (size_t)(wn0 + 32 * h) * ND + 2 * j;
#pragma unroll
        for (int g = 0; g < 4; g++) {
            wpre[h * 8 + g * 2 + 0] = *(const float2*)(wr + 16 * g);
            wpre[h * 8 + g * 2 + 1] = *(const float2*)(wr + 16 * g + 8);
        }
    }
#pragma unroll
    for (int h = 0; h < 2; h++) {
        int n = wn0 + 32 * h;
#pragma unroll
        for (int g = 0; g < 4; g++) {
            uint32_t h0, m0, h1, m1;
            float2 p0 = wpre[h * 8 + g * 2], p1 = wpre[h * 8 + g * 2 + 1];
            cvt_split_pair(p0.x, p0.y, h0, m0);
            cvt_split_pair(p1.x, p1.y, h1, m1);
            char* d = smem + (g * 64 + n) * 32 + j * 8;
            *(uint2*)(d)         = make_uint2(h0, h1);
            *(uint2*)(d + PLANE) = make_uint2(m0, m1);
        }
    }
    __syncthreads();

    // ---- main loop over K stages ----
    for (int s = 0; s < NSTAGE; s++) {
        if (s + 1 < NSTAGE) {
            const int kn = (s + 1) * KC;
#pragma unroll
            for (int h = 0; h < 2; h++) {
                const float* wr = W + (size_t)(wn0 + 32 * h) * ND + kn + 2 * j;
#pragma unroll
                for (int g = 0; g < 4; g++) {
                    wpre[h * 8 + g * 2 + 0] = *(const float2*)(wr + 16 * g);
                    wpre[h * 8 + g * 2 + 1] = *(const float2*)(wr + 16 * g + 8);
                }
            }
        }

        const char* buf = smem + (s & 1) * BUFB;
        const int k0 = s * KC;

        float2 a0 = *(const float2*)(aRow + k0);
        float2 a1 = *(const float2*)(aRow + 8 * ND + k0);
        float2 a2 = *(const float2*)(aRow + k0 + 8);
        float2 a3 = *(const float2*)(aRow + 8 * ND + k0 + 8);

#pragma unroll
        for (int g = 0; g < 4; g++) {
            float2 p0, p1, p2, p3;
            if (g < 3) {
                const int kg = k0 + 16 * (g + 1);
                p0 = *(const float2*)(aRow + kg);
                p1 = *(const float2*)(aRow + 8 * ND + kg);
                p2 = *(const float2*)(aRow + kg + 8);
                p3 = *(const float2*)(aRow + 8 * ND + kg + 8);
            }
            uint32_t aH[4], aM[4];
            cvt_split_pair(a0.x, a0.y, aH[0], aM[0]);
            cvt_split_pair(a1.x, a1.y, aH[1], aM[1]);
            cvt_split_pair(a2.x, a2.y, aH[2], aM[2]);
            cvt_split_pair(a3.x, a3.y, aH[3], aM[3]);

            const char* bb = buf + (size_t)(g * 64 + qr) * 32 + j * 8;

            // front-batched b-fragment loads (MLP), then 3 spaced MMA sweeps
            uint2 bh[8], bm[8];
#pragma unroll
            for (int t = 0; t < 8; t++) {
                bh[t] = *(const uint2*)(bb + t * 256);
                bm[t] = *(const uint2*)(bb + t * 256 + PLANE);
            }
#pragma unroll
            for (int t = 0; t < 8; t++) MMA(acc[t], aH, bh[t].x, bh[t].y);
#pragma unroll
            for (int t = 0; t < 8; t++) MMA(acc[t], aM, bh[t].x, bh[t].y);
#pragma unroll
            for (int t = 0; t < 8; t++) MMA(acc[t], aH, bm[t].x, bm[t].y);

            if (g < 3) { a0 = p0; a1 = p1; a2 = p2; a3 = p3; }
        }

        if (s + 1 < NSTAGE) {
            char* nb = smem + ((s + 1) & 1) * BUFB;
#pragma unroll
            for (int h = 0; h < 2; h++) {
                int n = wn0 + 32 * h;
#pragma unroll
                for (int g = 0; g < 4; g++) {
                    uint32_t h0, m0, h1, m1;
                    float2 p0 = wpre[h * 8 + g * 2], p1 = wpre[h * 8 + g * 2 + 1];
                    cvt_split_pair(p0.x, p0.y, h0, m0);
                    cvt_split_pair(p1.x, p1.y, h1, m1);
                    char* d = nb + (g * 64 + n) * 32 + j * 8;
                    *(uint2*)(d)         = make_uint2(h0, h1);
                    *(uint2*)(d + PLANE) = make_uint2(m0, m1);
                }
            }
            __syncthreads();
        }
    }

    // ---- epilogue: per-row top-2 + softmax, register-only + shfl merge ----
#pragma unroll
    for (int half = 0; half < 2; half++) {
        float m1 = -3.4e38f, m2 = -3.4e38f;
        int i1 = 0, i2 = 0;
#pragma unroll
        for (int t = 0; t < 8; t++) {
#pragma unroll
            for (int c = 0; c < 2; c++) {
                float v = acc[t][half * 2 + c];
                int e = 8 * t + 2 * j + c;
                if (v > m1) { m2 = m1; i2 = i1; m1 = v; i1 = e; }
                else if (v > m2) { m2 = v; i2 = e; }
            }
        }
#pragma unroll
        for (int off = 1; off <= 2; off <<= 1) {
            float om1 = __shfl_xor_sync(0xffffffffu, m1, off);
            float om2 = __shfl_xor_sync(0xffffffffu, m2, off);
            int   oi1 = __shfl_xor_sync(0xffffffffu, i1, off);
            int   oi2 = __shfl_xor_sync(0xffffffffu, i2, off);
            if (om1 > m1) {
                float nm2 = (om2 > m1) ? om2 : m1;
                int   ni2 = (om2 > m1) ? oi2 : i1;
                m1 = om1; i1 = oi1; m2 = nm2; i2 = ni2;
            } else if (om1 > m2) {
                m2 = om1; i2 = oi1;
            }
        }
        if (j == 0) {
            int tok = tok0 + warp * 16 + qr + half * 8;
            float ex = __expf(m2 - m1);
            float s1 = 1.0f / (1.0f + ex);
            out[2 * tok]     = s1;
            out[2 * tok + 1] = ex * s1;
            out[2 * NTOK + 2 * tok]     = (float)i1;
            out[2 * NTOK + 2 * tok + 1] = (float)i2;
        }
    }
}

extern "C" void kernel_launch(void* const* d_in, const int* in_sizes, int n_in,
                              void* d_out, int out_size)
{
    const float* hs = (const float*)d_in[0];   // (4, 4096, 4096) fp32
    const float* W  = (const float*)d_in[1];   // (64, 4096) fp32
    float* out      = (float*)d_out;           // [scores 32768][indices 32768]
    (void)in_sizes; (void)n_in; (void)out_size;

    topk_router_kernel<<<NTOK / TOK_CTA, NTHREADS>>>(hs, W, out);
}

// round 10
// speedup vs baseline: 1.7287x; 1.3227x over previous
#include <cuda_runtime.h>
#include <cstdint>

#define ND 4096
#define NE 64
#define NTOK 16384
#define TOK_CTA 64
#define NTHREADS 128
#define KC 64
#define NSTAGE (ND / KC)        // 64
// B plane: [4 g][64 n][4 j] uint2, g-block 2048B + 32B pad -> g-stride 2080
#define GSTR 2080
#define PLANE (4 * GSTR)        // 8320
#define BUFB (2 * PLANE)        // hi, mid planes = 16640

// round-to-nearest fp16 2-way split: h = hi + mid + q, |q| <= 2^-22|h|, unbiased.
__device__ __forceinline__ void cvt_split_pair(float h0, float h1,
                                               uint32_t& hi2, uint32_t& mid2) {
    asm("cvt.rn.f16x2.f32 %0, %1, %2;" : "=r"(hi2) : "f"(h1), "f"(h0));   // lo half = h0
    float f0, f1;
    asm("{.reg .f16 a, b;\n\t mov.b32 {a, b}, %2;\n\t"
        "cvt.f32.f16 %0, a;\n\t cvt.f32.f16 %1, b;}"
        : "=f"(f0), "=f"(f1) : "r"(hi2));
    float r0 = h0 - f0;
    float r1 = h1 - f1;
    asm("cvt.rn.f16x2.f32 %0, %1, %2;" : "=r"(mid2) : "f"(r1), "f"(r0));
}

#define MMA(c, a, b0_, b1_) \
    asm volatile("mma.sync.aligned.m16n8k16.row.col.f32.f16.f16.f32 " \
        "{%0,%1,%2,%3}, {%4,%5,%6,%7}, {%8,%9}, {%0,%1,%2,%3};" \
        : "+f"((c)[0]), "+f"((c)[1]), "+f"((c)[2]), "+f"((c)[3]) \
        : "r"((a)[0]), "r"((a)[1]), "r"((a)[2]), "r"((a)[3]), "r"(b0_), "r"(b1_))

__global__ __launch_bounds__(NTHREADS, 2)
void topk_router_kernel(const float* __restrict__ hs,
                        const float* __restrict__ W,
                        float* __restrict__ out)
{
    __shared__ __align__(16) char smem[2 * BUFB];   // 33280 B

    const int tid  = threadIdx.x;
    const int lane = tid & 31;
    const int warp = tid >> 5;
    const int j    = lane & 3;     // k-slot selector
    const int qr   = lane >> 2;    // row / n selector
    const int tok0 = blockIdx.x * TOK_CTA;

    // W loader: coalesced float4; (g, j) slot derived from column
    const int wc = tid & 15;               // float4 column 0..15
    const int wr = tid >> 4;               // row base 0..7 (rows wr + 8p)
    const int wg = wc >> 2, wj = wc & 3;
    const float* wBase = W + (size_t)wr * ND + 4 * wc;

    // A: permuted-K fragment loads; global col = 16g + 4j + {0..3}
    const float* a0p = hs + (size_t)(tok0 + warp * 16 + qr) * ND + 4 * j;
    const float* a1p = a0p + 8 * ND;

    float acc[8][4];
#pragma unroll
    for (int t = 0; t < 8; t++)
#pragma unroll
        for (int c = 0; c < 4; c++) acc[t][c] = 0.f;

    float4 wpre[8];

    // ---- prologue: W stage 0 (coalesced load + convert + fragment STS) ----
#pragma unroll
    for (int p = 0; p < 8; p++) wpre[p] = *(const float4*)(wBase + p * 8 * ND);
#pragma unroll
    for (int p = 0; p < 8; p++) {
        uint32_t h0, m0, h1, m1;
        cvt_split_pair(wpre[p].x, wpre[p].y, h0, m0);
        cvt_split_pair(wpre[p].z, wpre[p].w, h1, m1);
        char* d = smem + wg * GSTR + (wr + 8 * p) * 32 + wj * 8;
        *(uint2*)(d)         = make_uint2(h0, h1);
        *(uint2*)(d + PLANE) = make_uint2(m0, m1);
    }
    // A prologue: (s0,g0) and (s0,g1)
    float4 cur0 = *(const float4*)(a0p);
    float4 cur1 = *(const float4*)(a1p);
    float4 nx0  = *(const float4*)(a0p + 16);
    float4 nx1  = *(const float4*)(a1p + 16);
    __syncthreads();

    // ---- main loop over K stages ----
    for (int s = 0; s < NSTAGE; s++) {
        if (s + 1 < NSTAGE) {
            const int ko = (s + 1) * KC;
#pragma unroll
            for (int p = 0; p < 8; p++)
                wpre[p] = *(const float4*)(wBase + p * 8 * ND + ko);
        }

        const char* buf = smem + (s & 1) * BUFB;

#pragma unroll
        for (int g = 0; g < 4; g++) {
            // distance-2 A prefetch: (s, g+2) or (s+1, g-2)
            float4 p0, p1;
            bool havePf;
            int pfoff = 0;
            if (g < 2)                 { havePf = true; pfoff = s * KC + (g + 2) * 16; }
            else if (s + 1 < NSTAGE)   { havePf = true; pfoff = (s + 1) * KC + (g - 2) * 16; }
            else                       { havePf = false; }
            if (havePf) {
                p0 = *(const float4*)(a0p + pfoff);
                p1 = *(const float4*)(a1p + pfoff);
            }

            uint32_t aH[4], aM[4];
            cvt_split_pair(cur0.x, cur0.y, aH[0], aM[0]);   // slot 2j,   row qr
            cvt_split_pair(cur1.x, cur1.y, aH[1], aM[1]);   // slot 2j,   row qr+8
            cvt_split_pair(cur0.z, cur0.w, aH[2], aM[2]);   // slot 2j+8, row qr
            cvt_split_pair(cur1.z, cur1.w, aH[3], aM[3]);   // slot 2j+8, row qr+8

            const char* bb = buf + g * GSTR + qr * 32 + j * 8;
            uint2 bh[8], bm[8];
#pragma unroll
            for (int t = 0; t < 8; t++) {
                bh[t] = *(const uint2*)(bb + t * 256);
                bm[t] = *(const uint2*)(bb + t * 256 + PLANE);
            }
#pragma unroll
            for (int t = 0; t < 8; t++) MMA(acc[t], aH, bh[t].x, bh[t].y);
#pragma unroll
            for (int t = 0; t < 8; t++) MMA(acc[t], aM, bh[t].x, bh[t].y);
#pragma unroll
            for (int t = 0; t < 8; t++) MMA(acc[t], aH, bm[t].x, bm[t].y);

            cur0 = nx0; cur1 = nx1;
            if (havePf) { nx0 = p0; nx1 = p1; }
        }

        if (s + 1 < NSTAGE) {
            char* nb = smem + ((s + 1) & 1) * BUFB;
#pragma unroll
            for (int p = 0; p < 8; p++) {
                uint32_t h0, m0, h1, m1;
                cvt_split_pair(wpre[p].x, wpre[p].y, h0, m0);
                cvt_split_pair(wpre[p].z, wpre[p].w, h1, m1);
                char* d = nb + wg * GSTR + (wr + 8 * p) * 32 + wj * 8;
                *(uint2*)(d)         = make_uint2(h0, h1);
                *(uint2*)(d + PLANE) = make_uint2(m0, m1);
            }
            __syncthreads();
        }
    }

    // ---- epilogue: per-row top-2 + softmax, register-only + shfl merge ----
#pragma unroll
    for (int half = 0; half < 2; half++) {
        float m1 = -3.4e38f, m2 = -3.4e38f;
        int i1 = 0, i2 = 0;
#pragma unroll
        for (int t = 0; t < 8; t++) {
#pragma unroll
            for (int c = 0; c < 2; c++) {
                float v = acc[t][half * 2 + c];
                int e = 8 * t + 2 * j + c;
                if (v > m1) { m2 = m1; i2 = i1; m1 = v; i1 = e; }
                else if (v > m2) { m2 = v; i2 = e; }
            }
        }
#pragma unroll
        for (int off = 1; off <= 2; off <<= 1) {
            float om1 = __shfl_xor_sync(0xffffffffu, m1, off);
            float om2 = __shfl_xor_sync(0xffffffffu, m2, off);
            int   oi1 = __shfl_xor_sync(0xffffffffu, i1, off);
            int   oi2 = __shfl_xor_sync(0xffffffffu, i2, off);
            if (om1 > m1) {
                float nm2 = (om2 > m1) ? om2 : m1;
                int   ni2 = (om2 > m1) ? oi2 : i1;
                m1 = om1; i1 = oi1; m2 = nm2; i2 = ni2;
            } else if (om1 > m2) {
                m2 = om1; i2 = oi1;
            }
        }
        if (j == 0) {
            int tok = tok0 + warp * 16 + qr + half * 8;
            float ex = __expf(m2 - m1);
            float s1 = 1.0f / (1.0f + ex);
            out[2 * tok]     = s1;
            out[2 * tok + 1] = ex * s1;
            out[2 * NTOK + 2 * tok]     = (float)i1;
            out[2 * NTOK + 2 * tok + 1] = (float)i2;
        }
    }
}

extern "C" void kernel_launch(void* const* d_in, const int* in_sizes, int n_in,
                              void* d_out, int out_size)
{
    const float* hs = (const float*)d_in[0];   // (4, 4096, 4096) fp32
    const float* W  = (const float*)d_in[1];   // (64, 4096) fp32
    float* out      = (float*)d_out;           // [scores 32768][indices 32768]
    (void)in_sizes; (void)n_in; (void)out_size;

    topk_router_kernel<<<NTOK / TOK_CTA, NTHREADS>>>(hs, W, out);
}